// round 16
// baseline (speedup 1.0000x reference)
#include <cuda_runtime.h>
#include <cuda_fp16.h>
#include <cstdint>
#include <math.h>

#define FDIM 128
#define NMAX 20000
#define EMAX 320000
#define CAP  64              // bucket capacity per node (Poisson(16): P(>64)~1e-20)

typedef unsigned long long ull;
typedef unsigned int       u32;

// ---------------- scratch ----------------------------------------------------
__device__ __half g_hh[NMAX * FDIM];         // h = silu(q@W1+b1), fp16
__device__ __half g_ctxh[NMAX * 3 * FDIM];   // ctx fp16
__device__ __half g_muh[NMAX * 3 * FDIM];    // mu fp16
__device__ __half g_w1t[FDIM * FDIM];        // W1^T fp16 [n][k]
__device__ __half g_w2t[3 * FDIM * FDIM];    // W2^T fp16 [n][k]
__device__ int    g_counts[NMAX];            // per-node edge counts (atomic)
__device__ float4 g_edata[NMAX * CAP];       // {j, dx, dy, dz} bucketed
__device__ int    g_perm[NMAX * CAP];        // edge id bucketed

// ---------------- float4 / half helpers --------------------------------------
__device__ __forceinline__ float4 f4mul(float4 a, float4 b) {
    return make_float4(a.x*b.x, a.y*b.y, a.z*b.z, a.w*b.w);
}
__device__ __forceinline__ float4 f4fma(float4 a, float4 b, float4 c) {
    return make_float4(fmaf(a.x,b.x,c.x), fmaf(a.y,b.y,c.y),
                       fmaf(a.z,b.z,c.z), fmaf(a.w,b.w,c.w));
}
__device__ __forceinline__ float4 f4fmas(float4 a, float s, float4 c) {
    return make_float4(fmaf(a.x,s,c.x), fmaf(a.y,s,c.y),
                       fmaf(a.z,s,c.z), fmaf(a.w,s,c.w));
}
__device__ __forceinline__ float4 h4tof4(uint2 u) {
    __half2 a = *(__half2*)&u.x, b = *(__half2*)&u.y;
    float2 fa = __half22float2(a), fb = __half22float2(b);
    return make_float4(fa.x, fa.y, fb.x, fb.y);
}
__device__ __forceinline__ void prefetch_l2(const void* p) {
    asm volatile("prefetch.global.L2 [%0];" :: "l"(p));
}

// ---------------- mma/ldmatrix helpers (sm_80+ baseline) ---------------------
__device__ __forceinline__ u32 smem_u32(const void* p) {
    u32 a;
    asm("{ .reg .u64 t; cvta.to.shared.u64 t, %1; cvt.u32.u64 %0, t; }"
        : "=r"(a) : "l"(p));
    return a;
}
__device__ __forceinline__ void ldsm_x4(u32* r, u32 addr) {
    asm volatile("ldmatrix.sync.aligned.m8n8.x4.shared.b16 {%0,%1,%2,%3}, [%4];"
                 : "=r"(r[0]), "=r"(r[1]), "=r"(r[2]), "=r"(r[3]) : "r"(addr));
}
__device__ __forceinline__ void ldsm_x2(u32* r, u32 addr) {
    asm volatile("ldmatrix.sync.aligned.m8n8.x2.shared.b16 {%0,%1}, [%2];"
                 : "=r"(r[0]), "=r"(r[1]) : "r"(addr));
}
__device__ __forceinline__ void mma16816(float* d, const u32* a, const u32* b) {
    asm volatile(
        "mma.sync.aligned.m16n8k16.row.col.f32.f16.f16.f32 "
        "{%0,%1,%2,%3}, {%4,%5,%6,%7}, {%8,%9}, {%0,%1,%2,%3};"
        : "+f"(d[0]), "+f"(d[1]), "+f"(d[2]), "+f"(d[3])
        : "r"(a[0]), "r"(a[1]), "r"(a[2]), "r"(a[3]), "r"(b[0]), "r"(b[1]));
}

#define HM_LD 136   // smem row stride in halves (272B: conflict-free ldmatrix)

// ---------------- weight prep: W1^T and W2^T to fp16 --------------------------
__global__ void w_prep(const float* __restrict__ W1, const float* __restrict__ W2) {
    int i = blockIdx.x * blockDim.x + threadIdx.x;
    if (i < FDIM * FDIM) {
        int nn = i >> 7, kk = i & 127;
        g_w1t[i] = __float2half(W1[kk * 128 + nn]);
    } else if (i < 4 * FDIM * FDIM) {
        int j = i - FDIM * FDIM;
        int nn = j >> 7, kk = j & 127;
        g_w2t[j] = __float2half(W2[kk * 384 + nn]);
    }
}

// ---------------- mu -> fp16 -----------------------------------------------
__global__ void mu_to_half(const float4* __restrict__ mu4, int total4) {
    int i = blockIdx.x * blockDim.x + threadIdx.x;
    if (i < total4) {
        float4 v = __ldcs(&mu4[i]);
        __half2 p0 = __floats2half2_rn(v.x, v.y);
        __half2 p1 = __floats2half2_rn(v.z, v.w);
        uint2 u; u.x = *(unsigned*)&p0; u.y = *(unsigned*)&p1;
        ((uint2*)g_muh)[i] = u;
    }
}

// ---------------- GEMM1: h = silu(q @ W1 + b1) via HMMA -----------------------
#define H1_B_OFF (128 * HM_LD * 2)
#define H1_SMEM  (H1_B_OFF + 128 * HM_LD * 2)

__global__ void __launch_bounds__(256, 2)
gemm1_hmma(const float* __restrict__ q, const float* __restrict__ b1, int n) {
    extern __shared__ __align__(16) char smemc[];
    __half* As = (__half*)smemc;
    __half* Bs = (__half*)(smemc + H1_B_OFF);
    u32 sbA = smem_u32(As);
    u32 sbB = smem_u32(Bs);

    int tid = threadIdx.x, wid = tid >> 5, lane = tid & 31;
    int row0 = blockIdx.x * 128;

    {
        const float4* src = (const float4*)q;
#pragma unroll
        for (int i = tid; i < 4096; i += 256) {
            int r = i >> 5, c4 = i & 31;
            float4 v = (row0 + r < n) ? __ldg(&src[(size_t)(row0 + r) * 32 + c4])
                                      : make_float4(0.f, 0.f, 0.f, 0.f);
            __half2 p0 = __floats2half2_rn(v.x, v.y);
            __half2 p1 = __floats2half2_rn(v.z, v.w);
            uint2 u; u.x = *(unsigned*)&p0; u.y = *(unsigned*)&p1;
            *(uint2*)(As + r * HM_LD + c4 * 4) = u;
        }
    }
    {
        const uint4* src = (const uint4*)g_w1t;
#pragma unroll
        for (int i = tid; i < 2048; i += 256) {
            int r = i >> 4, c16 = i & 15;
            *(uint4*)(Bs + r * HM_LD + c16 * 8) = __ldg(&src[i]);
        }
    }
    __syncthreads();

    int m0  = wid * 16;
    int l16 = lane & 15;
    int a_row  = m0 + l16;
    int a_koff = (lane >> 4) << 3;
    int b_noff = l16 & 7;
    int b_koff = (l16 >> 3) << 3;
    int tr = lane >> 2;
    int tc = (lane & 3) << 1;

    float acc[16][4];
#pragma unroll
    for (int nt = 0; nt < 16; nt++)
#pragma unroll
        for (int c = 0; c < 4; c++) acc[nt][c] = 0.f;

#pragma unroll
    for (int ks = 0; ks < 8; ks++) {
        u32 a[4];
        ldsm_x4(a, sbA + (u32)((a_row * HM_LD + ks * 16 + a_koff) * 2));
#pragma unroll
        for (int nt = 0; nt < 16; nt++) {
            u32 b[2];
            int brow = nt * 8 + b_noff;
            ldsm_x2(b, sbB + (u32)((brow * HM_LD + ks * 16 + b_koff) * 2));
            mma16816(acc[nt], a, b);
        }
    }

#pragma unroll
    for (int nt = 0; nt < 16; nt++) {
        int col = nt * 8 + tc;
        float bb0 = __ldg(&b1[col]), bb1 = __ldg(&b1[col + 1]);
        int r0 = row0 + m0 + tr;
        int r1 = r0 + 8;
        if (r0 < n) {
            float f0 = acc[nt][0] + bb0, f1 = acc[nt][1] + bb1;
            f0 = f0 / (1.f + __expf(-f0));
            f1 = f1 / (1.f + __expf(-f1));
            *(__half2*)&g_hh[(size_t)r0 * FDIM + col] = __floats2half2_rn(f0, f1);
        }
        if (r1 < n) {
            float f0 = acc[nt][2] + bb0, f1 = acc[nt][3] + bb1;
            f0 = f0 / (1.f + __expf(-f0));
            f1 = f1 / (1.f + __expf(-f1));
            *(__half2*)&g_hh[(size_t)r1 * FDIM + col] = __floats2half2_rn(f0, f1);
        }
    }
}

// ---------------- GEMM2: ctx = h @ W2 + b2 via HMMA (grid.y = ntile) ----------
#define H2_B_OFF (128 * HM_LD * 2)
#define H2_SMEM  (H2_B_OFF + 128 * HM_LD * 2)

__global__ void __launch_bounds__(256, 2)
gemm2_hmma(const float* __restrict__ b2, int n) {
    extern __shared__ __align__(16) char smemc[];
    __half* As = (__half*)smemc;
    __half* Bs = (__half*)(smemc + H2_B_OFF);
    u32 sbA = smem_u32(As);
    u32 sbB = smem_u32(Bs);

    int tid = threadIdx.x, wid = tid >> 5, lane = tid & 31;
    int row0  = blockIdx.x * 128;
    int ntile = blockIdx.y;

    {
        const uint4* src = (const uint4*)(g_hh + (size_t)row0 * FDIM);
#pragma unroll
        for (int i = tid; i < 2048; i += 256) {
            int r = i >> 4, c16 = i & 15;
            uint4 v = (row0 + r < n) ? __ldg(&src[i]) : make_uint4(0, 0, 0, 0);
            *(uint4*)(As + r * HM_LD + c16 * 8) = v;
        }
    }
    {
        const uint4* src = (const uint4*)(g_w2t + (size_t)ntile * 128 * FDIM);
#pragma unroll
        for (int i = tid; i < 2048; i += 256) {
            int r = i >> 4, c16 = i & 15;
            *(uint4*)(Bs + r * HM_LD + c16 * 8) = __ldg(&src[i]);
        }
    }
    __syncthreads();

    int m0  = wid * 16;
    int l16 = lane & 15;
    int a_row  = m0 + l16;
    int a_koff = (lane >> 4) << 3;
    int b_noff = l16 & 7;
    int b_koff = (l16 >> 3) << 3;
    int tr = lane >> 2;
    int tc = (lane & 3) << 1;

    float acc[16][4];
#pragma unroll
    for (int nt = 0; nt < 16; nt++)
#pragma unroll
        for (int c = 0; c < 4; c++) acc[nt][c] = 0.f;

#pragma unroll
    for (int ks = 0; ks < 8; ks++) {
        u32 a[4];
        ldsm_x4(a, sbA + (u32)((a_row * HM_LD + ks * 16 + a_koff) * 2));
#pragma unroll
        for (int nt = 0; nt < 16; nt++) {
            u32 b[2];
            int brow = nt * 8 + b_noff;
            ldsm_x2(b, sbB + (u32)((brow * HM_LD + ks * 16 + b_koff) * 2));
            mma16816(acc[nt], a, b);
        }
    }

#pragma unroll
    for (int nt = 0; nt < 16; nt++) {
        int col = ntile * 128 + nt * 8 + tc;
        float bb0 = __ldg(&b2[col]), bb1 = __ldg(&b2[col + 1]);
        int r0 = row0 + m0 + tr;
        int r1 = r0 + 8;
        if (r0 < n) {
            __half2 p = __floats2half2_rn(acc[nt][0] + bb0, acc[nt][1] + bb1);
            *(__half2*)&g_ctxh[(size_t)r0 * 384 + col] = p;
        }
        if (r1 < n) {
            __half2 p = __floats2half2_rn(acc[nt][2] + bb0, acc[nt][3] + bb1);
            *(__half2*)&g_ctxh[(size_t)r1 * 384 + col] = p;
        }
    }
}

// ---------------- bucket scatter ----------------------------------------------
__global__ void scatter_bucket(const int* __restrict__ idx_i,
                               const int* __restrict__ idx_j,
                               const float* __restrict__ dir_ij, int E) {
    int e = blockIdx.x * blockDim.x + threadIdx.x;
    if (e < E) {
        int i = idx_i[e];
        int pos = atomicAdd(&g_counts[i], 1);
        if (pos < CAP) {
            int slot = i * CAP + pos;
            float4 ed;
            ed.x = __int_as_float(idx_j[e]);
            ed.y = dir_ij[e * 3 + 0];
            ed.z = dir_ij[e * 3 + 1];
            ed.w = dir_ij[e * 3 + 2];
            g_edata[slot] = ed;
            g_perm[slot]  = e;
        }
    }
}

// ---------------- aggregation: warp/node, 2-pair-deep W prefetch --------------
__global__ void __launch_bounds__(256)
aggregate(const float* __restrict__ q, const float* __restrict__ mu,
          const float* __restrict__ W_ij, float* __restrict__ out, int n) {
    int warp = (blockIdx.x * blockDim.x + threadIdx.x) >> 5;
    int lane = threadIdx.x & 31;
    if (warp >= n) return;
    int node = warp;

    const float4* Q4  = (const float4*)q;
    const float4* MU4 = (const float4*)mu;
    const float4* W4  = (const float4*)W_ij;
    const uint2*  CH  = (const uint2*)g_ctxh;
    const uint2*  MH  = (const uint2*)g_muh;

    float4 aq  = __ldg(&Q4[(size_t)node * 32 + lane]);
    float4 am0 = __ldg(&MU4[(size_t)node * 96 + lane]);
    float4 am1 = __ldg(&MU4[(size_t)node * 96 + 32 + lane]);
    float4 am2 = __ldg(&MU4[(size_t)node * 96 + 64 + lane]);

    int cnt = __ldg(&g_counts[node]);
    if (cnt > CAP) cnt = CAP;
    int base = node * CAP;
    int p = 0;

    // 2-pair-deep index pipeline: A,B = current pair; C,D = next pair (ready)
    float4 edA, edB, edC, edD;
    int eA = 0, eB = 0, eC = 0, eD = 0;
    if (cnt > 0) { edA = __ldcs(&g_edata[base]);     eA = __ldcs(&g_perm[base]); }
    if (cnt > 1) { edB = __ldcs(&g_edata[base + 1]); eB = __ldcs(&g_perm[base + 1]); }
    if (cnt > 2) { edC = __ldcs(&g_edata[base + 2]); eC = __ldcs(&g_perm[base + 2]); }
    if (cnt > 3) { edD = __ldcs(&g_edata[base + 3]); eD = __ldcs(&g_perm[base + 3]); }
    // warm L2 for the first pair's W rows (one-time stall on eA/eB is fine)
    if (cnt > 0) {
        const float4* w = &W4[(size_t)eA * 96 + lane];
        prefetch_l2(w); prefetch_l2(w + 32); prefetch_l2(w + 64);
    }
    if (cnt > 1) {
        const float4* w = &W4[(size_t)eB * 96 + lane];
        prefetch_l2(w); prefetch_l2(w + 32); prefetch_l2(w + 64);
    }

    // main loop: pairs p, p+1, p+2 all fully resident (6 edges ahead)
    for (; p + 5 < cnt; p += 2) {
        // prefetch W for NEXT pair using indices loaded last iteration (no stall)
        {
            const float4* wp0 = &W4[(size_t)eC * 96 + lane];
            const float4* wp1 = &W4[(size_t)eD * 96 + lane];
            prefetch_l2(wp0); prefetch_l2(wp0 + 32); prefetch_l2(wp0 + 64);
            prefetch_l2(wp1); prefetch_l2(wp1 + 32); prefetch_l2(wp1 + 64);
        }
        // load indices 2 pairs ahead
        float4 edE = __ldcs(&g_edata[base + p + 4]);
        int    eE  = __ldcs(&g_perm[base + p + 4]);
        float4 edF = __ldcs(&g_edata[base + p + 5]);
        int    eF  = __ldcs(&g_perm[base + p + 5]);

        float4 ed0 = edA, ed1 = edB;
        int e0 = eA, e1 = eB;

        size_t bw0 = (size_t)e0 * 96;
        size_t bw1 = (size_t)e1 * 96;
        float4 w00 = __ldcs(&W4[bw0 + lane]);
        float4 w01 = __ldcs(&W4[bw0 + 32 + lane]);
        float4 w02 = __ldcs(&W4[bw0 + 64 + lane]);
        float4 w10 = __ldcs(&W4[bw1 + lane]);
        float4 w11 = __ldcs(&W4[bw1 + 32 + lane]);
        float4 w12 = __ldcs(&W4[bw1 + 64 + lane]);

        int j0 = __float_as_int(ed0.x);
        int j1 = __float_as_int(ed1.x);
        size_t bc0 = (size_t)j0 * 96;
        size_t bc1 = (size_t)j1 * 96;
        uint2 uc00 = __ldg(&CH[bc0 + lane]);
        uint2 uc01 = __ldg(&CH[bc0 + 32 + lane]);
        uint2 uc02 = __ldg(&CH[bc0 + 64 + lane]);
        uint2 uc10 = __ldg(&CH[bc1 + lane]);
        uint2 uc11 = __ldg(&CH[bc1 + 32 + lane]);
        uint2 uc12 = __ldg(&CH[bc1 + 64 + lane]);

        uint2 um00 = __ldg(&MH[bc0 + lane]);
        uint2 um01 = __ldg(&MH[bc0 + 32 + lane]);
        uint2 um02 = __ldg(&MH[bc0 + 64 + lane]);
        uint2 um10 = __ldg(&MH[bc1 + lane]);
        uint2 um11 = __ldg(&MH[bc1 + 32 + lane]);
        uint2 um12 = __ldg(&MH[bc1 + 64 + lane]);

        aq = f4fma(w00, h4tof4(uc00), aq);
        float4 r0  = f4mul(w01, h4tof4(uc01));
        float4 mm0 = f4mul(w02, h4tof4(uc02));
        am0 = f4fma(mm0, h4tof4(um00), f4fmas(r0, ed0.y, am0));
        am1 = f4fma(mm0, h4tof4(um01), f4fmas(r0, ed0.z, am1));
        am2 = f4fma(mm0, h4tof4(um02), f4fmas(r0, ed0.w, am2));

        aq = f4fma(w10, h4tof4(uc10), aq);
        float4 r1  = f4mul(w11, h4tof4(uc11));
        float4 mm1 = f4mul(w12, h4tof4(uc12));
        am0 = f4fma(mm1, h4tof4(um10), f4fmas(r1, ed1.y, am0));
        am1 = f4fma(mm1, h4tof4(um11), f4fmas(r1, ed1.z, am1));
        am2 = f4fma(mm1, h4tof4(um12), f4fmas(r1, ed1.w, am2));

        // shift pipeline
        edA = edC; eA = eC; edB = edD; eB = eD;
        edC = edE; eC = eE; edD = edF; eD = eF;
    }

    // tail: remaining <=5 edges, simple loads
    for (; p < cnt; p++) {
        float4 ed = __ldcs(&g_edata[base + p]);
        int e = __ldcs(&g_perm[base + p]);
        int j = __float_as_int(ed.x);
        size_t bw = (size_t)e * 96;
        float4 w0 = __ldcs(&W4[bw + lane]);
        float4 w1 = __ldcs(&W4[bw + 32 + lane]);
        float4 w2 = __ldcs(&W4[bw + 64 + lane]);
        size_t bc = (size_t)j * 96;
        float4 c0 = h4tof4(__ldg(&CH[bc + lane]));
        float4 c1 = h4tof4(__ldg(&CH[bc + 32 + lane]));
        float4 c2 = h4tof4(__ldg(&CH[bc + 64 + lane]));
        float4 mj0 = h4tof4(__ldg(&MH[bc + lane]));
        float4 mj1 = h4tof4(__ldg(&MH[bc + 32 + lane]));
        float4 mj2 = h4tof4(__ldg(&MH[bc + 64 + lane]));
        aq = f4fma(w0, c0, aq);
        float4 r  = f4mul(w1, c1);
        float4 mm = f4mul(w2, c2);
        am0 = f4fma(mm, mj0, f4fmas(r, ed.y, am0));
        am1 = f4fma(mm, mj1, f4fmas(r, ed.z, am1));
        am2 = f4fma(mm, mj2, f4fmas(r, ed.w, am2));
    }

    float4* outq  = (float4*)out;
    float4* outmu = (float4*)(out + (size_t)n * FDIM);
    __stcs(&outq[(size_t)node * 32 + lane], aq);
    __stcs(&outmu[(size_t)node * 96 + lane],      am0);
    __stcs(&outmu[(size_t)node * 96 + 32 + lane], am1);
    __stcs(&outmu[(size_t)node * 96 + 64 + lane], am2);
}

// ---------------- launch -------------------------------------------------------
extern "C" void kernel_launch(void* const* d_in, const int* in_sizes, int n_in,
                              void* d_out, int out_size) {
    const float* q      = (const float*)d_in[0];
    const float* mu     = (const float*)d_in[1];
    const float* W_ij   = (const float*)d_in[2];
    const float* dir_ij = (const float*)d_in[3];
    const float* W1     = (const float*)d_in[4];
    const float* b1     = (const float*)d_in[5];
    const float* W2     = (const float*)d_in[6];
    const float* b2     = (const float*)d_in[7];
    const int*   idx_i  = (const int*)d_in[8];
    const int*   idx_j  = (const int*)d_in[9];

    int n = in_sizes[0] / FDIM;       // 20000
    int E = in_sizes[8];              // 320000

    static int* counts_ptr = nullptr;
    static cudaStream_t s2 = nullptr, s3 = nullptr;
    static cudaEvent_t evFork = nullptr, evJoin2 = nullptr, evJoin3 = nullptr;
    if (!counts_ptr) {
        cudaGetSymbolAddress((void**)&counts_ptr, g_counts);
        cudaStreamCreateWithFlags(&s2, cudaStreamNonBlocking);
        cudaStreamCreateWithFlags(&s3, cudaStreamNonBlocking);
        cudaEventCreateWithFlags(&evFork,  cudaEventDisableTiming);
        cudaEventCreateWithFlags(&evJoin2, cudaEventDisableTiming);
        cudaEventCreateWithFlags(&evJoin3, cudaEventDisableTiming);
        cudaFuncSetAttribute((const void*)gemm1_hmma,
                             cudaFuncAttributeMaxDynamicSharedMemorySize, H1_SMEM);
        cudaFuncSetAttribute((const void*)gemm2_hmma,
                             cudaFuncAttributeMaxDynamicSharedMemorySize, H2_SMEM);
    }

    // fork
    cudaEventRecord(evFork, 0);
    cudaStreamWaitEvent(s2, evFork, 0);
    cudaStreamWaitEvent(s3, evFork, 0);

    // main: weight prep + HMMA GEMM1 + HMMA GEMM2
    w_prep<<<(4 * FDIM * FDIM + 255) / 256, 256>>>(W1, W2);
    int gb = (n + 127) / 128;
    gemm1_hmma<<<gb, 256, H1_SMEM>>>(q, b1, n);
    gemm2_hmma<<<dim3(gb, 3), 256, H2_SMEM>>>(b2, n);

    // s2: bucket CSR (no histogram, no scan)
    cudaMemsetAsync(counts_ptr, 0, (size_t)n * sizeof(int), s2);
    scatter_bucket<<<(E + 255) / 256, 256, 0, s2>>>(idx_i, idx_j, dir_ij, E);

    // s3: mu fp16 conversion
    int total4 = n * 96;
    mu_to_half<<<(total4 + 255) / 256, 256, 0, s3>>>((const float4*)mu, total4);

    // join
    cudaEventRecord(evJoin2, s2);
    cudaEventRecord(evJoin3, s3);
    cudaStreamWaitEvent(0, evJoin2, 0);
    cudaStreamWaitEvent(0, evJoin3, 0);

    int agg_blocks = (n * 32 + 255) / 256;
    aggregate<<<agg_blocks, 256>>>(q, mu, W_ij, (float*)d_out, n);
}

// round 17
// speedup vs baseline: 1.0657x; 1.0657x over previous
#include <cuda_runtime.h>
#include <cuda_fp16.h>
#include <cstdint>
#include <math.h>

#define FDIM 128
#define NMAX 20000
#define EMAX 320000
#define CAP  64              // bucket capacity per node (Poisson(16): P(>64)~1e-20)

typedef unsigned long long ull;
typedef unsigned int       u32;

// ---------------- scratch ----------------------------------------------------
__device__ __half g_hh[NMAX * FDIM];         // h = silu(q@W1+b1), fp16
__device__ __half g_ctxh[NMAX * 3 * FDIM];   // ctx fp16
__device__ __half g_muh[NMAX * 3 * FDIM];    // mu fp16
__device__ __half g_w1t[FDIM * FDIM];        // W1^T fp16 [n][k]
__device__ __half g_w2t[3 * FDIM * FDIM];    // W2^T fp16 [n][k]
__device__ int    g_counts[NMAX];            // per-node edge counts (atomic)
__device__ float4 g_edata[NMAX * CAP];       // {j, dx, dy, dz} bucketed
__device__ int    g_perm[NMAX * CAP];        // edge id bucketed

// ---------------- float4 / half helpers --------------------------------------
__device__ __forceinline__ float4 f4mul(float4 a, float4 b) {
    return make_float4(a.x*b.x, a.y*b.y, a.z*b.z, a.w*b.w);
}
__device__ __forceinline__ float4 f4fma(float4 a, float4 b, float4 c) {
    return make_float4(fmaf(a.x,b.x,c.x), fmaf(a.y,b.y,c.y),
                       fmaf(a.z,b.z,c.z), fmaf(a.w,b.w,c.w));
}
__device__ __forceinline__ float4 f4fmas(float4 a, float s, float4 c) {
    return make_float4(fmaf(a.x,s,c.x), fmaf(a.y,s,c.y),
                       fmaf(a.z,s,c.z), fmaf(a.w,s,c.w));
}
__device__ __forceinline__ float4 h4tof4(uint2 u) {
    __half2 a = *(__half2*)&u.x, b = *(__half2*)&u.y;
    float2 fa = __half22float2(a), fb = __half22float2(b);
    return make_float4(fa.x, fa.y, fb.x, fb.y);
}
__device__ __forceinline__ void prefetch_l2(const void* p) {
    asm volatile("prefetch.global.L2 [%0];" :: "l"(p));
}

// ---------------- mma/ldmatrix helpers (sm_80+ baseline) ---------------------
__device__ __forceinline__ u32 smem_u32(const void* p) {
    u32 a;
    asm("{ .reg .u64 t; cvta.to.shared.u64 t, %1; cvt.u32.u64 %0, t; }"
        : "=r"(a) : "l"(p));
    return a;
}
__device__ __forceinline__ void ldsm_x4(u32* r, u32 addr) {
    asm volatile("ldmatrix.sync.aligned.m8n8.x4.shared.b16 {%0,%1,%2,%3}, [%4];"
                 : "=r"(r[0]), "=r"(r[1]), "=r"(r[2]), "=r"(r[3]) : "r"(addr));
}
__device__ __forceinline__ void ldsm_x2(u32* r, u32 addr) {
    asm volatile("ldmatrix.sync.aligned.m8n8.x2.shared.b16 {%0,%1}, [%2];"
                 : "=r"(r[0]), "=r"(r[1]) : "r"(addr));
}
__device__ __forceinline__ void mma16816(float* d, const u32* a, const u32* b) {
    asm volatile(
        "mma.sync.aligned.m16n8k16.row.col.f32.f16.f16.f32 "
        "{%0,%1,%2,%3}, {%4,%5,%6,%7}, {%8,%9}, {%0,%1,%2,%3};"
        : "+f"(d[0]), "+f"(d[1]), "+f"(d[2]), "+f"(d[3])
        : "r"(a[0]), "r"(a[1]), "r"(a[2]), "r"(a[3]), "r"(b[0]), "r"(b[1]));
}

#define HM_LD 136   // smem row stride in halves (272B: conflict-free ldmatrix)

// ---------------- weight prep: W1^T and W2^T to fp16 --------------------------
__global__ void w_prep(const float* __restrict__ W1, const float* __restrict__ W2) {
    int i = blockIdx.x * blockDim.x + threadIdx.x;
    if (i < FDIM * FDIM) {
        int nn = i >> 7, kk = i & 127;
        g_w1t[i] = __float2half(W1[kk * 128 + nn]);
    } else if (i < 4 * FDIM * FDIM) {
        int j = i - FDIM * FDIM;
        int nn = j >> 7, kk = j & 127;
        g_w2t[j] = __float2half(W2[kk * 384 + nn]);
    }
}

// ---------------- mu -> fp16 -----------------------------------------------
__global__ void mu_to_half(const float4* __restrict__ mu4, int total4) {
    int i = blockIdx.x * blockDim.x + threadIdx.x;
    if (i < total4) {
        float4 v = __ldcs(&mu4[i]);
        __half2 p0 = __floats2half2_rn(v.x, v.y);
        __half2 p1 = __floats2half2_rn(v.z, v.w);
        uint2 u; u.x = *(unsigned*)&p0; u.y = *(unsigned*)&p1;
        ((uint2*)g_muh)[i] = u;
    }
}

// ---------------- GEMM1: h = silu(q @ W1 + b1) via HMMA -----------------------
#define H1_B_OFF (128 * HM_LD * 2)
#define H1_SMEM  (H1_B_OFF + 128 * HM_LD * 2)

__global__ void __launch_bounds__(256, 2)
gemm1_hmma(const float* __restrict__ q, const float* __restrict__ b1, int n) {
    extern __shared__ __align__(16) char smemc[];
    __half* As = (__half*)smemc;
    __half* Bs = (__half*)(smemc + H1_B_OFF);
    u32 sbA = smem_u32(As);
    u32 sbB = smem_u32(Bs);

    int tid = threadIdx.x, wid = tid >> 5, lane = tid & 31;
    int row0 = blockIdx.x * 128;

    {
        const float4* src = (const float4*)q;
#pragma unroll
        for (int i = tid; i < 4096; i += 256) {
            int r = i >> 5, c4 = i & 31;
            float4 v = (row0 + r < n) ? __ldg(&src[(size_t)(row0 + r) * 32 + c4])
                                      : make_float4(0.f, 0.f, 0.f, 0.f);
            __half2 p0 = __floats2half2_rn(v.x, v.y);
            __half2 p1 = __floats2half2_rn(v.z, v.w);
            uint2 u; u.x = *(unsigned*)&p0; u.y = *(unsigned*)&p1;
            *(uint2*)(As + r * HM_LD + c4 * 4) = u;
        }
    }
    {
        const uint4* src = (const uint4*)g_w1t;
#pragma unroll
        for (int i = tid; i < 2048; i += 256) {
            int r = i >> 4, c16 = i & 15;
            *(uint4*)(Bs + r * HM_LD + c16 * 8) = __ldg(&src[i]);
        }
    }
    __syncthreads();

    int m0  = wid * 16;
    int l16 = lane & 15;
    int a_row  = m0 + l16;
    int a_koff = (lane >> 4) << 3;
    int b_noff = l16 & 7;
    int b_koff = (l16 >> 3) << 3;
    int tr = lane >> 2;
    int tc = (lane & 3) << 1;

    float acc[16][4];
#pragma unroll
    for (int nt = 0; nt < 16; nt++)
#pragma unroll
        for (int c = 0; c < 4; c++) acc[nt][c] = 0.f;

#pragma unroll
    for (int ks = 0; ks < 8; ks++) {
        u32 a[4];
        ldsm_x4(a, sbA + (u32)((a_row * HM_LD + ks * 16 + a_koff) * 2));
#pragma unroll
        for (int nt = 0; nt < 16; nt++) {
            u32 b[2];
            int brow = nt * 8 + b_noff;
            ldsm_x2(b, sbB + (u32)((brow * HM_LD + ks * 16 + b_koff) * 2));
            mma16816(acc[nt], a, b);
        }
    }

#pragma unroll
    for (int nt = 0; nt < 16; nt++) {
        int col = nt * 8 + tc;
        float bb0 = __ldg(&b1[col]), bb1 = __ldg(&b1[col + 1]);
        int r0 = row0 + m0 + tr;
        int r1 = r0 + 8;
        if (r0 < n) {
            float f0 = acc[nt][0] + bb0, f1 = acc[nt][1] + bb1;
            f0 = f0 / (1.f + __expf(-f0));
            f1 = f1 / (1.f + __expf(-f1));
            *(__half2*)&g_hh[(size_t)r0 * FDIM + col] = __floats2half2_rn(f0, f1);
        }
        if (r1 < n) {
            float f0 = acc[nt][2] + bb0, f1 = acc[nt][3] + bb1;
            f0 = f0 / (1.f + __expf(-f0));
            f1 = f1 / (1.f + __expf(-f1));
            *(__half2*)&g_hh[(size_t)r1 * FDIM + col] = __floats2half2_rn(f0, f1);
        }
    }
}

// ---------------- GEMM2: ctx = h @ W2 + b2 via HMMA (grid.y = ntile) ----------
#define H2_B_OFF (128 * HM_LD * 2)
#define H2_SMEM  (H2_B_OFF + 128 * HM_LD * 2)

__global__ void __launch_bounds__(256, 2)
gemm2_hmma(const float* __restrict__ b2, int n) {
    extern __shared__ __align__(16) char smemc[];
    __half* As = (__half*)smemc;
    __half* Bs = (__half*)(smemc + H2_B_OFF);
    u32 sbA = smem_u32(As);
    u32 sbB = smem_u32(Bs);

    int tid = threadIdx.x, wid = tid >> 5, lane = tid & 31;
    int row0  = blockIdx.x * 128;
    int ntile = blockIdx.y;

    {
        const uint4* src = (const uint4*)(g_hh + (size_t)row0 * FDIM);
#pragma unroll
        for (int i = tid; i < 2048; i += 256) {
            int r = i >> 4, c16 = i & 15;
            uint4 v = (row0 + r < n) ? __ldg(&src[i]) : make_uint4(0, 0, 0, 0);
            *(uint4*)(As + r * HM_LD + c16 * 8) = v;
        }
    }
    {
        const uint4* src = (const uint4*)(g_w2t + (size_t)ntile * 128 * FDIM);
#pragma unroll
        for (int i = tid; i < 2048; i += 256) {
            int r = i >> 4, c16 = i & 15;
            *(uint4*)(Bs + r * HM_LD + c16 * 8) = __ldg(&src[i]);
        }
    }
    __syncthreads();

    int m0  = wid * 16;
    int l16 = lane & 15;
    int a_row  = m0 + l16;
    int a_koff = (lane >> 4) << 3;
    int b_noff = l16 & 7;
    int b_koff = (l16 >> 3) << 3;
    int tr = lane >> 2;
    int tc = (lane & 3) << 1;

    float acc[16][4];
#pragma unroll
    for (int nt = 0; nt < 16; nt++)
#pragma unroll
        for (int c = 0; c < 4; c++) acc[nt][c] = 0.f;

#pragma unroll
    for (int ks = 0; ks < 8; ks++) {
        u32 a[4];
        ldsm_x4(a, sbA + (u32)((a_row * HM_LD + ks * 16 + a_koff) * 2));
#pragma unroll
        for (int nt = 0; nt < 16; nt++) {
            u32 b[2];
            int brow = nt * 8 + b_noff;
            ldsm_x2(b, sbB + (u32)((brow * HM_LD + ks * 16 + b_koff) * 2));
            mma16816(acc[nt], a, b);
        }
    }

#pragma unroll
    for (int nt = 0; nt < 16; nt++) {
        int col = ntile * 128 + nt * 8 + tc;
        float bb0 = __ldg(&b2[col]), bb1 = __ldg(&b2[col + 1]);
        int r0 = row0 + m0 + tr;
        int r1 = r0 + 8;
        if (r0 < n) {
            __half2 p = __floats2half2_rn(acc[nt][0] + bb0, acc[nt][1] + bb1);
            *(__half2*)&g_ctxh[(size_t)r0 * 384 + col] = p;
        }
        if (r1 < n) {
            __half2 p = __floats2half2_rn(acc[nt][2] + bb0, acc[nt][3] + bb1);
            *(__half2*)&g_ctxh[(size_t)r1 * 384 + col] = p;
        }
    }
}

// ---------------- bucket scatter ----------------------------------------------
__global__ void scatter_bucket(const int* __restrict__ idx_i,
                               const int* __restrict__ idx_j,
                               const float* __restrict__ dir_ij, int E) {
    int e = blockIdx.x * blockDim.x + threadIdx.x;
    if (e < E) {
        int i = idx_i[e];
        int pos = atomicAdd(&g_counts[i], 1);
        if (pos < CAP) {
            int slot = i * CAP + pos;
            float4 ed;
            ed.x = __int_as_float(idx_j[e]);
            ed.y = dir_ij[e * 3 + 0];
            ed.z = dir_ij[e * 3 + 1];
            ed.w = dir_ij[e * 3 + 2];
            g_edata[slot] = ed;
            g_perm[slot]  = e;
        }
    }
}

// ---------------- aggregation: warp/node; perm-only 2-deep W prefetch ---------
// Same as the 151.6us kernel, plus ONLY two extra int registers (eC/eD) so the
// W-row prefetch consumes indices loaded a full iteration earlier (no stall).
__global__ void __launch_bounds__(256)
aggregate(const float* __restrict__ q, const float* __restrict__ mu,
          const float* __restrict__ W_ij, float* __restrict__ out, int n) {
    int warp = (blockIdx.x * blockDim.x + threadIdx.x) >> 5;
    int lane = threadIdx.x & 31;
    if (warp >= n) return;
    int node = warp;

    const float4* Q4  = (const float4*)q;
    const float4* MU4 = (const float4*)mu;
    const float4* W4  = (const float4*)W_ij;
    const uint2*  CH  = (const uint2*)g_ctxh;
    const uint2*  MH  = (const uint2*)g_muh;

    float4 aq  = __ldg(&Q4[(size_t)node * 32 + lane]);
    float4 am0 = __ldg(&MU4[(size_t)node * 96 + lane]);
    float4 am1 = __ldg(&MU4[(size_t)node * 96 + 32 + lane]);
    float4 am2 = __ldg(&MU4[(size_t)node * 96 + 64 + lane]);

    int cnt = __ldg(&g_counts[node]);
    if (cnt > CAP) cnt = CAP;
    int base = node * CAP;
    int p = 0;

    // edata 1-pair-deep (as in the 151.6 kernel); perm 2-pairs-deep (+2 regs)
    float4 edA, edB;
    int eA = 0, eB = 0, eC = 0, eD = 0;
    if (cnt > 0) { edA = __ldcs(&g_edata[base]);     eA = __ldcs(&g_perm[base]); }
    if (cnt > 1) { edB = __ldcs(&g_edata[base + 1]); eB = __ldcs(&g_perm[base + 1]); }
    if (cnt > 2) eC = __ldcs(&g_perm[base + 2]);
    if (cnt > 3) eD = __ldcs(&g_perm[base + 3]);
    // warm L2 for the first pair's W rows (one-time stall acceptable)
    if (cnt > 0) {
        const float4* w = &W4[(size_t)eA * 96 + lane];
        prefetch_l2(w); prefetch_l2(w + 32); prefetch_l2(w + 64);
    }
    if (cnt > 1) {
        const float4* w = &W4[(size_t)eB * 96 + lane];
        prefetch_l2(w); prefetch_l2(w + 32); prefetch_l2(w + 64);
    }

    for (; p + 5 < cnt; p += 2) {
        // prefetch next pair's W via eC/eD — loaded LAST iteration, no stall
        {
            const float4* wp0 = &W4[(size_t)eC * 96 + lane];
            const float4* wp1 = &W4[(size_t)eD * 96 + lane];
            prefetch_l2(wp0); prefetch_l2(wp0 + 32); prefetch_l2(wp0 + 64);
            prefetch_l2(wp1); prefetch_l2(wp1 + 32); prefetch_l2(wp1 + 64);
        }

        float4 ed0 = edA, ed1 = edB;
        int e0 = eA, e1 = eB;
        // refill: edata for next pair, perm for the pair after next
        edA = __ldcs(&g_edata[base + p + 2]);
        edB = __ldcs(&g_edata[base + p + 3]);
        int eN0 = __ldcs(&g_perm[base + p + 4]);
        int eN1 = __ldcs(&g_perm[base + p + 5]);

        size_t bw0 = (size_t)e0 * 96;
        size_t bw1 = (size_t)e1 * 96;
        float4 w00 = __ldcs(&W4[bw0 + lane]);
        float4 w01 = __ldcs(&W4[bw0 + 32 + lane]);
        float4 w02 = __ldcs(&W4[bw0 + 64 + lane]);
        float4 w10 = __ldcs(&W4[bw1 + lane]);
        float4 w11 = __ldcs(&W4[bw1 + 32 + lane]);
        float4 w12 = __ldcs(&W4[bw1 + 64 + lane]);

        int j0 = __float_as_int(ed0.x);
        int j1 = __float_as_int(ed1.x);
        size_t bc0 = (size_t)j0 * 96;
        size_t bc1 = (size_t)j1 * 96;
        uint2 uc00 = __ldg(&CH[bc0 + lane]);
        uint2 uc01 = __ldg(&CH[bc0 + 32 + lane]);
        uint2 uc02 = __ldg(&CH[bc0 + 64 + lane]);
        uint2 uc10 = __ldg(&CH[bc1 + lane]);
        uint2 uc11 = __ldg(&CH[bc1 + 32 + lane]);
        uint2 uc12 = __ldg(&CH[bc1 + 64 + lane]);

        uint2 um00 = __ldg(&MH[bc0 + lane]);
        uint2 um01 = __ldg(&MH[bc0 + 32 + lane]);
        uint2 um02 = __ldg(&MH[bc0 + 64 + lane]);
        uint2 um10 = __ldg(&MH[bc1 + lane]);
        uint2 um11 = __ldg(&MH[bc1 + 32 + lane]);
        uint2 um12 = __ldg(&MH[bc1 + 64 + lane]);

        aq = f4fma(w00, h4tof4(uc00), aq);
        float4 r0  = f4mul(w01, h4tof4(uc01));
        float4 mm0 = f4mul(w02, h4tof4(uc02));
        am0 = f4fma(mm0, h4tof4(um00), f4fmas(r0, ed0.y, am0));
        am1 = f4fma(mm0, h4tof4(um01), f4fmas(r0, ed0.z, am1));
        am2 = f4fma(mm0, h4tof4(um02), f4fmas(r0, ed0.w, am2));

        aq = f4fma(w10, h4tof4(uc10), aq);
        float4 r1  = f4mul(w11, h4tof4(uc11));
        float4 mm1 = f4mul(w12, h4tof4(uc12));
        am0 = f4fma(mm1, h4tof4(um10), f4fmas(r1, ed1.y, am0));
        am1 = f4fma(mm1, h4tof4(um11), f4fmas(r1, ed1.z, am1));
        am2 = f4fma(mm1, h4tof4(um12), f4fmas(r1, ed1.w, am2));

        // shift perm pipeline
        eA = eC; eB = eD; eC = eN0; eD = eN1;
    }

    // tail: remaining <=5 edges, simple loads
    for (; p < cnt; p++) {
        float4 ed = __ldcs(&g_edata[base + p]);
        int e = __ldcs(&g_perm[base + p]);
        int j = __float_as_int(ed.x);
        size_t bw = (size_t)e * 96;
        float4 w0 = __ldcs(&W4[bw + lane]);
        float4 w1 = __ldcs(&W4[bw + 32 + lane]);
        float4 w2 = __ldcs(&W4[bw + 64 + lane]);
        size_t bc = (size_t)j * 96;
        float4 c0 = h4tof4(__ldg(&CH[bc + lane]));
        float4 c1 = h4tof4(__ldg(&CH[bc + 32 + lane]));
        float4 c2 = h4tof4(__ldg(&CH[bc + 64 + lane]));
        float4 mj0 = h4tof4(__ldg(&MH[bc + lane]));
        float4 mj1 = h4tof4(__ldg(&MH[bc + 32 + lane]));
        float4 mj2 = h4tof4(__ldg(&MH[bc + 64 + lane]));
        aq = f4fma(w0, c0, aq);
        float4 r  = f4mul(w1, c1);
        float4 mm = f4mul(w2, c2);
        am0 = f4fma(mm, mj0, f4fmas(r, ed.y, am0));
        am1 = f4fma(mm, mj1, f4fmas(r, ed.z, am1));
        am2 = f4fma(mm, mj2, f4fmas(r, ed.w, am2));
    }

    float4* outq  = (float4*)out;
    float4* outmu = (float4*)(out + (size_t)n * FDIM);
    __stcs(&outq[(size_t)node * 32 + lane], aq);
    __stcs(&outmu[(size_t)node * 96 + lane],      am0);
    __stcs(&outmu[(size_t)node * 96 + 32 + lane], am1);
    __stcs(&outmu[(size_t)node * 96 + 64 + lane], am2);
}

// ---------------- launch -------------------------------------------------------
extern "C" void kernel_launch(void* const* d_in, const int* in_sizes, int n_in,
                              void* d_out, int out_size) {
    const float* q      = (const float*)d_in[0];
    const float* mu     = (const float*)d_in[1];
    const float* W_ij   = (const float*)d_in[2];
    const float* dir_ij = (const float*)d_in[3];
    const float* W1     = (const float*)d_in[4];
    const float* b1     = (const float*)d_in[5];
    const float* W2     = (const float*)d_in[6];
    const float* b2     = (const float*)d_in[7];
    const int*   idx_i  = (const int*)d_in[8];
    const int*   idx_j  = (const int*)d_in[9];

    int n = in_sizes[0] / FDIM;       // 20000
    int E = in_sizes[8];              // 320000

    static int* counts_ptr = nullptr;
    static cudaStream_t s2 = nullptr, s3 = nullptr;
    static cudaEvent_t evFork = nullptr, evJoin2 = nullptr, evJoin3 = nullptr;
    if (!counts_ptr) {
        cudaGetSymbolAddress((void**)&counts_ptr, g_counts);
        cudaStreamCreateWithFlags(&s2, cudaStreamNonBlocking);
        cudaStreamCreateWithFlags(&s3, cudaStreamNonBlocking);
        cudaEventCreateWithFlags(&evFork,  cudaEventDisableTiming);
        cudaEventCreateWithFlags(&evJoin2, cudaEventDisableTiming);
        cudaEventCreateWithFlags(&evJoin3, cudaEventDisableTiming);
        cudaFuncSetAttribute((const void*)gemm1_hmma,
                             cudaFuncAttributeMaxDynamicSharedMemorySize, H1_SMEM);
        cudaFuncSetAttribute((const void*)gemm2_hmma,
                             cudaFuncAttributeMaxDynamicSharedMemorySize, H2_SMEM);
    }

    // fork
    cudaEventRecord(evFork, 0);
    cudaStreamWaitEvent(s2, evFork, 0);
    cudaStreamWaitEvent(s3, evFork, 0);

    // main: weight prep + HMMA GEMM1 + HMMA GEMM2
    w_prep<<<(4 * FDIM * FDIM + 255) / 256, 256>>>(W1, W2);
    int gb = (n + 127) / 128;
    gemm1_hmma<<<gb, 256, H1_SMEM>>>(q, b1, n);
    gemm2_hmma<<<dim3(gb, 3), 256, H2_SMEM>>>(b2, n);

    // s2: bucket CSR (no histogram, no scan)
    cudaMemsetAsync(counts_ptr, 0, (size_t)n * sizeof(int), s2);
    scatter_bucket<<<(E + 255) / 256, 256, 0, s2>>>(idx_i, idx_j, dir_ij, E);

    // s3: mu fp16 conversion
    int total4 = n * 96;
    mu_to_half<<<(total4 + 255) / 256, 256, 0, s3>>>((const float4*)mu, total4);

    // join
    cudaEventRecord(evJoin2, s2);
    cudaEventRecord(evJoin3, s3);
    cudaStreamWaitEvent(0, evJoin2, 0);
    cudaStreamWaitEvent(0, evJoin3, 0);

    int agg_blocks = (n * 32 + 255) / 256;
    aggregate<<<agg_blocks, 256>>>(q, mu, W_ij, (float*)d_out, n);
}